// round 3
// baseline (speedup 1.0000x reference)
#include <cuda_runtime.h>
#include <cstdint>
#include <cstddef>

// Problem constants (B=8, S=24, N=4096, K=9, C1=32, C2=16)
#define BS_TOT 192
#define SDIM   24
#define NPTS   4096
#define KNB    9
#define C1V    32
#define C2V    16
#define JTOT   36864   // KNB * NPTS
#define BN_EPS 1e-5f

// ---------------- device scratch (static globals: allocation-free) ----------
__device__ __align__(16) unsigned short d_P[JTOT];   // gather offsets, pre-scaled *8
__device__ float g_sum[SDIM * C2V];
__device__ float g_sumsq[SDIM * C2V];
__device__ float g_A[SDIM * C2V];
__device__ float g_B[SDIM * C2V];
__device__ float g_y2[(size_t)BS_TOT * C2V * NPTS];  // stage-2 output (48 MB)

// ---------------- packed f32x2 helpers (sm_103a FFMA2 path) ----------------
__device__ __forceinline__ unsigned long long pack2(float x, float y) {
    unsigned long long r;
    asm("mov.b64 %0, {%1, %2};" : "=l"(r)
        : "r"(__float_as_uint(x)), "r"(__float_as_uint(y)));
    return r;
}
__device__ __forceinline__ float2 unpack2(unsigned long long v) {
    unsigned int a, b;
    asm("mov.b64 {%0, %1}, %2;" : "=r"(a), "=r"(b) : "l"(v));
    return make_float2(__uint_as_float(a), __uint_as_float(b));
}
#define FMA2(acc, a, b) \
    asm("fma.rn.f32x2 %0, %1, %2, %0;" : "+l"(acc) : "l"(a), "l"(b))

// ---------------- K0: build permutation (pre-scaled byte offsets *8) --------
__global__ void k0_prep(const int* __restrict__ neigh) {
    int j = blockIdx.x * 256 + threadIdx.x;
    if (j < JTOT) {
        int n = j & (NPTS - 1);
        int k = j >> 12;
        d_P[j] = (unsigned short)(neigh[n * KNB + k] * 8);  // float2 byte offset
    }
    if (j < SDIM * C2V) { g_sum[j] = 0.f; g_sumsq[j] = 0.f; }
}

// ---------------- K2: fused stage1 + gather + GEMM + BN stats ---------------
// Block (bs, cb): computes h channels c0=2cb, c1=2cb+1 in smem (float2
// interleaved), then y2 for p' in [cb*256, cb*256+256). Thread t handles
// p'_a = cb*256+t (channel c0) and p'_b = cb*256+128+t (channel c1); both
// use the SAME gather row (row t of d_P), so ONE LDS.64 feeds both streams.
__global__ void __launch_bounds__(128) k2_fused(
    const float* __restrict__ in,
    const float* __restrict__ W1, const float* __restrict__ b1,
    const float* __restrict__ W2, const float* __restrict__ b2)
{
    extern __shared__ char smem[];
    float2* sh_h = (float2*)smem;                                    // 32 KB
    unsigned long long* sh_w = (unsigned long long*)(smem + 32768);  // 18 KB
    float* red_s = (float*)(smem + 32768 + 18432);                   // 4*16
    float* red_q = red_s + 64;                                       // 4*16

    int blk = blockIdx.x;
    int bs  = blk >> 4;
    int cb  = blk & 15;
    int c0  = 2 * cb;
    int t   = threadIdx.x;

    // --- load W2 pairs into smem: sh_w[q*8+oh] = (W2[2oh][q], W2[2oh+1][q])
    for (int i = t; i < 288 * 8; i += 128) {
        int q = i >> 3, oh = i & 7;
        sh_w[i] = pack2(W2[(2 * oh) * 288 + q], W2[(2 * oh + 1) * 288 + q]);
    }

    // --- stage 1: compute h[c0][p], h[c1][p] for all p, store as float2
    {
        unsigned long long w1p[KNB];
#pragma unroll
        for (int q = 0; q < KNB; q++)
            w1p[q] = pack2(__ldg(W1 + c0 * KNB + q), __ldg(W1 + (c0 + 1) * KNB + q));
        unsigned long long b1p = pack2(__ldg(b1 + c0), __ldg(b1 + c0 + 1));

        const float* ip = in + (size_t)bs * JTOT;
#pragma unroll 4
        for (int i = 0; i < 32; i++) {
            int p = t + (i << 7);
            unsigned long long acc = b1p;
            int base = p * KNB;
#pragma unroll
            for (int q = 0; q < KNB; q++) {
                int jt = base + q;
                float v = __ldg(ip + ((jt & (NPTS - 1)) * KNB) + (jt >> 12));
                FMA2(acc, pack2(v, v), w1p[q]);
            }
            float2 f = unpack2(acc);
            sh_h[p] = make_float2(fmaxf(f.x, 0.f), fmaxf(f.y, 0.f));
        }
    }
    __syncthreads();

    // --- stage 2: 288-tap gathered matvec, 16 outputs, two p' streams
    unsigned long long acc[16];
#pragma unroll
    for (int oh = 0; oh < 8; oh++) {
        unsigned long long bb = pack2(__ldg(b2 + 2 * oh), __ldg(b2 + 2 * oh + 1));
        acc[oh] = bb; acc[8 + oh] = bb;
    }

    const char* hbase = (const char*)sh_h;
    const uint4* Pp = (const uint4*)(d_P) + t * 36;   // row t: 288 u16 offsets
#pragma unroll 2
    for (int q8 = 0; q8 < 36; q8++) {
        uint4 pv = Pp[q8];
        unsigned off[8] = { pv.x & 0xFFFFu, pv.x >> 16,
                            pv.y & 0xFFFFu, pv.y >> 16,
                            pv.z & 0xFFFFu, pv.z >> 16,
                            pv.w & 0xFFFFu, pv.w >> 16 };
#pragma unroll
        for (int j = 0; j < 8; j++) {
            float2 hv = *(const float2*)(hbase + off[j]);   // one LDS.64, both channels
            unsigned long long ha = pack2(hv.x, hv.x);
            unsigned long long hb = pack2(hv.y, hv.y);
            const ulonglong2* w = (const ulonglong2*)(sh_w + (q8 * 8 + j) * 8);
#pragma unroll
            for (int oh2 = 0; oh2 < 4; oh2++) {
                ulonglong2 ww = w[oh2];
                FMA2(acc[2 * oh2],         ha, ww.x);
                FMA2(acc[2 * oh2 + 1],     ha, ww.y);
                FMA2(acc[8 + 2 * oh2],     hb, ww.x);
                FMA2(acc[8 + 2 * oh2 + 1], hb, ww.y);
            }
        }
    }

    float ya[16], yb[16];
#pragma unroll
    for (int oh = 0; oh < 8; oh++) {
        float2 fa = unpack2(acc[oh]);
        float2 fb = unpack2(acc[8 + oh]);
        ya[2 * oh] = fa.x; ya[2 * oh + 1] = fa.y;
        yb[2 * oh] = fb.x; yb[2 * oh + 1] = fb.y;
    }

    // write y2: layout g_y2[bs][o][p'],  p'_a = c0*128+t, p'_b = c0*128+128+t
    float* dst = g_y2 + (size_t)bs * (C2V * NPTS) + c0 * 128 + t;
#pragma unroll
    for (int o = 0; o < 16; o++) {
        dst[o * NPTS]       = ya[o];
        dst[o * NPTS + 128] = yb[o];
    }

    // BN partial sums over both streams
    int warp = t >> 5, lane = t & 31;
#pragma unroll
    for (int o = 0; o < 16; o++) {
        float v  = ya[o] + yb[o];
        float sq = ya[o] * ya[o] + yb[o] * yb[o];
#pragma unroll
        for (int off2 = 16; off2; off2 >>= 1) {
            v  += __shfl_down_sync(0xFFFFFFFFu, v,  off2);
            sq += __shfl_down_sync(0xFFFFFFFFu, sq, off2);
        }
        if (lane == 0) { red_s[warp * 16 + o] = v; red_q[warp * 16 + o] = sq; }
    }
    __syncthreads();
    if (t < 16) {
        float a = red_s[t] + red_s[16 + t] + red_s[32 + t] + red_s[48 + t];
        float q = red_q[t] + red_q[16 + t] + red_q[32 + t] + red_q[48 + t];
        int s = bs % SDIM;
        atomicAdd(&g_sum[s * C2V + t], a);
        atomicAdd(&g_sumsq[s * C2V + t], q);
    }
}

// ---------------- K2b: finalize BN scale/shift per (s, o) -------------------
__global__ void k2b_bnfinal(const float* __restrict__ gamma,
                            const float* __restrict__ beta)
{
    int i = threadIdx.x;
    if (i < SDIM * C2V) {
        const float cnt = 8.0f * (float)NPTS;   // B * N = 32768
        float mean = g_sum[i] / cnt;
        float var  = g_sumsq[i] / cnt - mean * mean;
        int o = i & 15;
        float A = gamma[o] * rsqrtf(var + BN_EPS);
        g_A[i] = A;
        g_B[i] = beta[o] - mean * A;
    }
}

// ---------------- K3: BN apply + relu + paired gather + 144-dot + relu ------
// Block (bs, cb): output channels o0=2cb, o1=2cb+1 as a float2-interleaved
// normalized slice. Thread t: p''_a = cb*512+t, p''_b = cb*512+256+t, same
// gather row t. One LDS.64 gather + one FFMA2 per tap covers both streams.
__global__ void __launch_bounds__(256) k3_stage3(
    const float* __restrict__ W3, const float* __restrict__ b3,
    float* __restrict__ out)
{
    __shared__ float2 sh_v[NPTS];                       // 32 KB
    __shared__ __align__(16) unsigned long long sw3p[144];

    int blk = blockIdx.x;
    int bs  = blk >> 3;
    int cb  = blk & 7;
    int o0  = 2 * cb;
    int t   = threadIdx.x;
    int s   = bs % SDIM;

    float A0 = g_A[s * C2V + o0],     B0 = g_B[s * C2V + o0];
    float A1 = g_A[s * C2V + o0 + 1], B1 = g_B[s * C2V + o0 + 1];

    const float4* s0 = (const float4*)(g_y2 + ((size_t)bs * C2V + o0) * NPTS);
    const float4* s1 = (const float4*)(g_y2 + ((size_t)bs * C2V + o0 + 1) * NPTS);
    for (int i = t; i < NPTS / 4; i += 256) {
        float4 a = s0[i];
        float4 b = s1[i];
        sh_v[4 * i + 0] = make_float2(fmaxf(fmaf(a.x, A0, B0), 0.f), fmaxf(fmaf(b.x, A1, B1), 0.f));
        sh_v[4 * i + 1] = make_float2(fmaxf(fmaf(a.y, A0, B0), 0.f), fmaxf(fmaf(b.y, A1, B1), 0.f));
        sh_v[4 * i + 2] = make_float2(fmaxf(fmaf(a.z, A0, B0), 0.f), fmaxf(fmaf(b.z, A1, B1), 0.f));
        sh_v[4 * i + 3] = make_float2(fmaxf(fmaf(a.w, A0, B0), 0.f), fmaxf(fmaf(b.w, A1, B1), 0.f));
    }
    if (t < 144) { float w = W3[t]; sw3p[t] = pack2(w, w); }
    __syncthreads();

    float bv = __ldg(b3);
    unsigned long long acc2 = pack2(bv, bv);
    const char* vbase = (const char*)sh_v;
    const uint4* Pp = (const uint4*)(d_P) + t * 18;  // row t: 144 u16 offsets
#pragma unroll 3
    for (int q8 = 0; q8 < 18; q8++) {
        uint4 pv = Pp[q8];
        unsigned off[8] = { pv.x & 0xFFFFu, pv.x >> 16,
                            pv.y & 0xFFFFu, pv.y >> 16,
                            pv.z & 0xFFFFu, pv.z >> 16,
                            pv.w & 0xFFFFu, pv.w >> 16 };
#pragma unroll
        for (int j = 0; j < 8; j++) {
            unsigned long long ab = *(const unsigned long long*)(vbase + off[j]);
            FMA2(acc2, ab, sw3p[q8 * 8 + j]);
        }
    }
    float2 r = unpack2(acc2);
    out[(size_t)bs * NPTS + cb * 512 + t]       = fmaxf(r.x, 0.f);
    out[(size_t)bs * NPTS + cb * 512 + 256 + t] = fmaxf(r.y, 0.f);
}

// ---------------- launch -----------------------------------------------------
extern "C" void kernel_launch(void* const* d_in, const int* in_sizes, int n_in,
                              void* d_out, int out_size)
{
    const float* input = (const float*)d_in[0];
    const int*   neigh = (const int*)  d_in[1];
    const float* W1    = (const float*)d_in[2];
    const float* b1    = (const float*)d_in[3];
    const float* W2    = (const float*)d_in[4];
    const float* b2    = (const float*)d_in[5];
    const float* gamma = (const float*)d_in[6];
    const float* beta  = (const float*)d_in[7];
    const float* W3    = (const float*)d_in[8];
    const float* b3    = (const float*)d_in[9];
    float* out = (float*)d_out;

    static int smem_set = 0;
    if (!smem_set) {
        cudaFuncSetAttribute(k2_fused, cudaFuncAttributeMaxDynamicSharedMemorySize,
                             32768 + 18432 + 512);
        smem_set = 1;
    }

    k0_prep<<<144, 256>>>(neigh);
    k2_fused<<<BS_TOT * 16, 128, 32768 + 18432 + 512>>>(input, W1, b1, W2, b2);
    k2b_bnfinal<<<1, 384>>>(gamma, beta);
    k3_stage3<<<BS_TOT * 8, 256>>>(W3, b3, out);
}

// round 4
// speedup vs baseline: 3.3393x; 3.3393x over previous
#include <cuda_runtime.h>
#include <cstdint>
#include <cstddef>

// Problem constants (B=8, S=24, N=4096, K=9, C1=32, C2=16)
#define BS_TOT 192
#define SDIM   24
#define NPTS   4096
#define KNB    9
#define C1V    32
#define C2V    16
#define JTOT   36864   // KNB * NPTS
#define BN_EPS 1e-5f

// ---------------- device scratch (static globals: allocation-free) ----------
__device__ __align__(16) unsigned short d_P[JTOT];  // gather byte-offsets (*16)
__device__ float g_sum[SDIM * C2V];
__device__ float g_sumsq[SDIM * C2V];
__device__ float g_A[SDIM * C2V];
__device__ float g_B[SDIM * C2V];
// h in 4-channel-interleaved layout: g_h4[(bs*8 + qb)*NPTS + p] = float4 of
// channels 4qb..4qb+3 at point p.  (96 MB)
__device__ float4 g_h4[(size_t)BS_TOT * 8 * NPTS];
__device__ float  g_y2[(size_t)BS_TOT * C2V * NPTS];  // stage-2 out (48 MB)

// ---------------- packed f32x2 helpers (sm_103a FFMA2 path) ----------------
__device__ __forceinline__ unsigned long long pack2(float x, float y) {
    unsigned long long r;
    asm("mov.b64 %0, {%1, %2};" : "=l"(r)
        : "r"(__float_as_uint(x)), "r"(__float_as_uint(y)));
    return r;
}
__device__ __forceinline__ float2 unpack2(unsigned long long v) {
    unsigned int a, b;
    asm("mov.b64 {%0, %1}, %2;" : "=r"(a), "=r"(b) : "l"(v));
    return make_float2(__uint_as_float(a), __uint_as_float(b));
}
#define FMA2(acc, a, b) \
    asm("fma.rn.f32x2 %0, %1, %2, %0;" : "+l"(acc) : "l"(a), "l"(b))

// ---------------- K0: build permutation (byte offsets *16 for float4) -------
__global__ void k0_prep(const int* __restrict__ neigh) {
    int j = blockIdx.x * 256 + threadIdx.x;
    if (j < JTOT) {
        int n = j & (NPTS - 1);
        int k = j >> 12;
        d_P[j] = (unsigned short)(neigh[n * KNB + k] * 16);
    }
    if (j < SDIM * C2V) { g_sum[j] = 0.f; g_sumsq[j] = 0.f; }
}

// ---------------- K1: stage 1 (9-tap conv, 32 channels, float4 layout) ------
__global__ void __launch_bounds__(256) k1_stage1(
    const float* __restrict__ in, const float* __restrict__ W1,
    const float* __restrict__ b1)
{
    __shared__ __align__(16) unsigned long long sw[KNB * 16];  // [q][oh] pairs
    __shared__ unsigned long long sb[16];
    int t = threadIdx.x;
    if (t < KNB * 16) {
        int q = t >> 4, oh = t & 15;
        sw[t] = pack2(W1[(2 * oh) * KNB + q], W1[(2 * oh + 1) * KNB + q]);
    }
    if (t < 16) sb[t] = pack2(b1[2 * t], b1[2 * t + 1]);
    __syncthreads();

    int g  = blockIdx.x * 256 + t;
    int bs = g >> 12;
    int pp = g & (NPTS - 1);
    const float* ip = in + (size_t)bs * JTOT;

    unsigned long long acc[16];
#pragma unroll
    for (int oh = 0; oh < 16; oh++) acc[oh] = sb[oh];

    int base = pp * KNB;
#pragma unroll
    for (int q = 0; q < KNB; q++) {
        int jt = base + q;
        float v = __ldg(ip + ((jt & (NPTS - 1)) * KNB) + (jt >> 12));
        unsigned long long v2 = pack2(v, v);
        const ulonglong2* w = (const ulonglong2*)(sw + q * 16);
#pragma unroll
        for (int oh2 = 0; oh2 < 8; oh2++) {
            ulonglong2 ww = w[oh2];
            FMA2(acc[2 * oh2],     v2, ww.x);
            FMA2(acc[2 * oh2 + 1], v2, ww.y);
        }
    }

    float4* hp = g_h4 + (size_t)bs * (8 * NPTS) + pp;
#pragma unroll
    for (int qb = 0; qb < 8; qb++) {
        float2 a = unpack2(acc[2 * qb]);
        float2 b = unpack2(acc[2 * qb + 1]);
        hp[qb * NPTS] = make_float4(fmaxf(a.x, 0.f), fmaxf(a.y, 0.f),
                                    fmaxf(b.x, 0.f), fmaxf(b.y, 0.f));
    }
}

// ---------------- K2: gather + GEMM (4 p'-streams/thread) + BN stats --------
// Block (bs, qb): channels c0=4qb..4qb+3 as float4 smem slice. Thread t
// handles p'_s = qb*512 + s*128 + t (s=0..3, channel 4qb+s); all four share
// gather row t of d_P, so ONE LDS.128 feeds four output streams.
__global__ void __launch_bounds__(128) k2_stage2(
    const float* __restrict__ W2, const float* __restrict__ b2)
{
    extern __shared__ char smem[];
    float4* sh_h = (float4*)smem;                                    // 64 KB
    unsigned long long* sh_w = (unsigned long long*)(smem + 65536);  // 18 KB
    float* red_s = (float*)(smem + 65536 + 18432);                   // 4*16
    float* red_q = red_s + 64;

    int blk = blockIdx.x;
    int bs  = blk >> 3;
    int qb  = blk & 7;
    int t   = threadIdx.x;

    // load h slice (coalesced float4) + W2 pairs
    const float4* hsrc = g_h4 + ((size_t)bs * 8 + qb) * NPTS;
    for (int i = t; i < NPTS; i += 128) sh_h[i] = hsrc[i];
    for (int i = t; i < 288 * 8; i += 128) {
        int q = i >> 3, oh = i & 7;
        sh_w[i] = pack2(W2[(2 * oh) * 288 + q], W2[(2 * oh + 1) * 288 + q]);
    }
    __syncthreads();

    unsigned long long acc[32];
#pragma unroll
    for (int oh = 0; oh < 8; oh++) {
        unsigned long long bb = pack2(__ldg(b2 + 2 * oh), __ldg(b2 + 2 * oh + 1));
        acc[oh] = bb; acc[8 + oh] = bb; acc[16 + oh] = bb; acc[24 + oh] = bb;
    }

    const char* hbase = (const char*)sh_h;
    const uint4* Pp = (const uint4*)(d_P) + t * 36;   // row t: 288 u16 offsets
#pragma unroll 2
    for (int q8 = 0; q8 < 36; q8++) {
        uint4 pv = Pp[q8];
        unsigned off[8] = { pv.x & 0xFFFFu, pv.x >> 16,
                            pv.y & 0xFFFFu, pv.y >> 16,
                            pv.z & 0xFFFFu, pv.z >> 16,
                            pv.w & 0xFFFFu, pv.w >> 16 };
#pragma unroll
        for (int j = 0; j < 8; j++) {
            float4 hv = *(const float4*)(hbase + off[j]);   // one LDS.128
            unsigned long long ha = pack2(hv.x, hv.x);
            unsigned long long hb = pack2(hv.y, hv.y);
            unsigned long long hc = pack2(hv.z, hv.z);
            unsigned long long hd = pack2(hv.w, hv.w);
            const ulonglong2* w = (const ulonglong2*)(sh_w + (q8 * 8 + j) * 8);
#pragma unroll
            for (int oh2 = 0; oh2 < 4; oh2++) {
                ulonglong2 ww = w[oh2];
                FMA2(acc[2 * oh2],          ha, ww.x);
                FMA2(acc[2 * oh2 + 1],      ha, ww.y);
                FMA2(acc[8 + 2 * oh2],      hb, ww.x);
                FMA2(acc[8 + 2 * oh2 + 1],  hb, ww.y);
                FMA2(acc[16 + 2 * oh2],     hc, ww.x);
                FMA2(acc[16 + 2 * oh2 + 1], hc, ww.y);
                FMA2(acc[24 + 2 * oh2],     hd, ww.x);
                FMA2(acc[24 + 2 * oh2 + 1], hd, ww.y);
            }
        }
    }

    // unpack, write y2, accumulate BN stats
    float* dst = g_y2 + (size_t)bs * (C2V * NPTS) + qb * 512 + t;
    float vsum[16], vsq[16];
#pragma unroll
    for (int o = 0; o < 16; o++) { vsum[o] = 0.f; vsq[o] = 0.f; }
#pragma unroll
    for (int s = 0; s < 4; s++) {
#pragma unroll
        for (int oh = 0; oh < 8; oh++) {
            float2 f = unpack2(acc[s * 8 + oh]);
            dst[(2 * oh) * NPTS + s * 128]     = f.x;
            dst[(2 * oh + 1) * NPTS + s * 128] = f.y;
            vsum[2 * oh]     += f.x;  vsq[2 * oh]     += f.x * f.x;
            vsum[2 * oh + 1] += f.y;  vsq[2 * oh + 1] += f.y * f.y;
        }
    }

    int warp = t >> 5, lane = t & 31;
#pragma unroll
    for (int o = 0; o < 16; o++) {
        float v = vsum[o], sq = vsq[o];
#pragma unroll
        for (int off2 = 16; off2; off2 >>= 1) {
            v  += __shfl_down_sync(0xFFFFFFFFu, v,  off2);
            sq += __shfl_down_sync(0xFFFFFFFFu, sq, off2);
        }
        if (lane == 0) { red_s[warp * 16 + o] = v; red_q[warp * 16 + o] = sq; }
    }
    __syncthreads();
    if (t < 16) {
        float a = red_s[t] + red_s[16 + t] + red_s[32 + t] + red_s[48 + t];
        float q = red_q[t] + red_q[16 + t] + red_q[32 + t] + red_q[48 + t];
        int s = bs % SDIM;
        atomicAdd(&g_sum[s * C2V + t], a);
        atomicAdd(&g_sumsq[s * C2V + t], q);
    }
}

// ---------------- K2b: finalize BN scale/shift per (s, o) -------------------
__global__ void k2b_bnfinal(const float* __restrict__ gamma,
                            const float* __restrict__ beta)
{
    int i = threadIdx.x;
    if (i < SDIM * C2V) {
        const float cnt = 8.0f * (float)NPTS;   // B * N = 32768
        float mean = g_sum[i] / cnt;
        float var  = g_sumsq[i] / cnt - mean * mean;
        int o = i & 15;
        float A = gamma[o] * rsqrtf(var + BN_EPS);
        g_A[i] = A;
        g_B[i] = beta[o] - mean * A;
    }
}

// ---------------- K3: BN+relu, 4-stream gather, 144-dot, relu ---------------
// Block (bs, cb4): channels o0=4cb4..o0+3, float4-interleaved normalized
// slice. Thread t: p''_s = cb4*1024 + s*256 + t (s=0..3), same gather row t.
// Per tap: ONE LDS.128 + one broadcast LDS.64 + 2 FFMA2 for four streams.
__global__ void __launch_bounds__(256) k3_stage3(
    const float* __restrict__ W3, const float* __restrict__ b3,
    float* __restrict__ out)
{
    extern __shared__ char smem3[];
    float4* sh_v = (float4*)smem3;                                   // 64 KB
    unsigned long long* sw3p = (unsigned long long*)(smem3 + 65536); // 144*8

    int blk = blockIdx.x;
    int bs  = blk >> 2;
    int cb4 = blk & 3;
    int o0  = 4 * cb4;
    int t   = threadIdx.x;
    int s   = bs % SDIM;

    float A0 = g_A[s * C2V + o0],     B0 = g_B[s * C2V + o0];
    float A1 = g_A[s * C2V + o0 + 1], B1 = g_B[s * C2V + o0 + 1];
    float A2 = g_A[s * C2V + o0 + 2], B2 = g_B[s * C2V + o0 + 2];
    float A3 = g_A[s * C2V + o0 + 3], B3 = g_B[s * C2V + o0 + 3];

    const float4* s0 = (const float4*)(g_y2 + ((size_t)bs * C2V + o0) * NPTS);
    const float4* s1 = (const float4*)(g_y2 + ((size_t)bs * C2V + o0 + 1) * NPTS);
    const float4* s2 = (const float4*)(g_y2 + ((size_t)bs * C2V + o0 + 2) * NPTS);
    const float4* s3 = (const float4*)(g_y2 + ((size_t)bs * C2V + o0 + 3) * NPTS);
    for (int i = t; i < NPTS / 4; i += 256) {
        float4 a = s0[i], b = s1[i], c = s2[i], d = s3[i];
        sh_v[4 * i + 0] = make_float4(fmaxf(fmaf(a.x, A0, B0), 0.f), fmaxf(fmaf(b.x, A1, B1), 0.f),
                                      fmaxf(fmaf(c.x, A2, B2), 0.f), fmaxf(fmaf(d.x, A3, B3), 0.f));
        sh_v[4 * i + 1] = make_float4(fmaxf(fmaf(a.y, A0, B0), 0.f), fmaxf(fmaf(b.y, A1, B1), 0.f),
                                      fmaxf(fmaf(c.y, A2, B2), 0.f), fmaxf(fmaf(d.y, A3, B3), 0.f));
        sh_v[4 * i + 2] = make_float4(fmaxf(fmaf(a.z, A0, B0), 0.f), fmaxf(fmaf(b.z, A1, B1), 0.f),
                                      fmaxf(fmaf(c.z, A2, B2), 0.f), fmaxf(fmaf(d.z, A3, B3), 0.f));
        sh_v[4 * i + 3] = make_float4(fmaxf(fmaf(a.w, A0, B0), 0.f), fmaxf(fmaf(b.w, A1, B1), 0.f),
                                      fmaxf(fmaf(c.w, A2, B2), 0.f), fmaxf(fmaf(d.w, A3, B3), 0.f));
    }
    if (t < 144) { float w = W3[t]; sw3p[t] = pack2(w, w); }
    __syncthreads();

    float bv = __ldg(b3);
    unsigned long long acc01 = pack2(bv, bv);
    unsigned long long acc23 = pack2(bv, bv);
    const char* vbase = (const char*)sh_v;
    const uint4* Pp = (const uint4*)(d_P) + t * 18;  // row t: 144 u16 offsets
#pragma unroll 3
    for (int q8 = 0; q8 < 18; q8++) {
        uint4 pv = Pp[q8];
        unsigned off[8] = { pv.x & 0xFFFFu, pv.x >> 16,
                            pv.y & 0xFFFFu, pv.y >> 16,
                            pv.z & 0xFFFFu, pv.z >> 16,
                            pv.w & 0xFFFFu, pv.w >> 16 };
#pragma unroll
        for (int j = 0; j < 8; j++) {
            ulonglong2 vv = *(const ulonglong2*)(vbase + off[j]);  // LDS.128
            unsigned long long ww = sw3p[q8 * 8 + j];
            FMA2(acc01, vv.x, ww);
            FMA2(acc23, vv.y, ww);
        }
    }
    float2 r01 = unpack2(acc01);
    float2 r23 = unpack2(acc23);
    float* op = out + (size_t)bs * NPTS + cb4 * 1024 + t;
    op[0]   = fmaxf(r01.x, 0.f);
    op[256] = fmaxf(r01.y, 0.f);
    op[512] = fmaxf(r23.x, 0.f);
    op[768] = fmaxf(r23.y, 0.f);
}

// ---------------- launch -----------------------------------------------------
extern "C" void kernel_launch(void* const* d_in, const int* in_sizes, int n_in,
                              void* d_out, int out_size)
{
    const float* input = (const float*)d_in[0];
    const int*   neigh = (const int*)  d_in[1];
    const float* W1    = (const float*)d_in[2];
    const float* b1    = (const float*)d_in[3];
    const float* W2    = (const float*)d_in[4];
    const float* b2    = (const float*)d_in[5];
    const float* gamma = (const float*)d_in[6];
    const float* beta  = (const float*)d_in[7];
    const float* W3    = (const float*)d_in[8];
    const float* b3    = (const float*)d_in[9];
    float* out = (float*)d_out;

    static int smem_set = 0;
    if (!smem_set) {
        cudaFuncSetAttribute(k2_stage2, cudaFuncAttributeMaxDynamicSharedMemorySize,
                             65536 + 18432 + 512);
        cudaFuncSetAttribute(k3_stage3, cudaFuncAttributeMaxDynamicSharedMemorySize,
                             65536 + 144 * 8);
        smem_set = 1;
    }

    k0_prep<<<144, 256>>>(neigh);
    k1_stage1<<<(BS_TOT * NPTS) / 256, 256>>>(input, W1, b1);
    k2_stage2<<<BS_TOT * 8, 128, 65536 + 18432 + 512>>>(W2, b2);
    k2b_bnfinal<<<1, 384>>>(gamma, beta);
    k3_stage3<<<BS_TOT * 4, 256, 65536 + 144 * 8>>>(W3, b3, out);
}